// round 14
// baseline (speedup 1.0000x reference)
#include <cuda_runtime.h>
#include <cuda_pipeline.h>

static constexpr int V = 1024;
static constexpr int THREADS = 1024;

__global__ void zero_out_kernel(float* out) {
    if (threadIdx.x == 0) out[0] = 0.0f;
}

__global__ void loss_kernel(const float* __restrict__ pred,
                            const int* __restrict__ tgt,
                            float* __restrict__ out, int B) {
    __shared__ float s_p[THREADS];
    int i = blockIdx.x * blockDim.x + threadIdx.x;

    // gather via cp.async (LDGSTS path: no register scoreboard, different
    // outstanding-miss tracking than LDG) — probes whether LDG miss-tracking
    // depth, not DRAM activates, was the binding resource
    if (i < B) {
        int t = __ldcg(&tgt[i]);
        __pipeline_memcpy_async(&s_p[threadIdx.x], &pred[(size_t)i * V + t], 4);
    }
    __pipeline_commit();
    __pipeline_wait_prior(0);
    __syncthreads();

    float v = (i < B) ? -__logf(s_p[threadIdx.x]) : 0.0f;

    // intra-warp reduction
    #pragma unroll
    for (int o = 16; o > 0; o >>= 1)
        v += __shfl_down_sync(0xffffffffu, v, o);

    __shared__ float smem[THREADS >> 5];
    int lane = threadIdx.x & 31;
    int warp = threadIdx.x >> 5;
    if (lane == 0) smem[warp] = v;
    __syncthreads();

    // first warp reduces the 32 warp partials, one atomic per block
    if (warp == 0) {
        v = smem[lane];
        #pragma unroll
        for (int o = 16; o > 0; o >>= 1)
            v += __shfl_down_sync(0xffffffffu, v, o);
        if (lane == 0) atomicAdd(out, v);
    }
}

extern "C" void kernel_launch(void* const* d_in, const int* in_sizes, int n_in,
                              void* d_out, int out_size) {
    const float* pred = (const float*)d_in[0];
    const int* tgt = (const int*)d_in[1];
    float* out = (float*)d_out;
    int B = in_sizes[1];

    zero_out_kernel<<<1, 32>>>(out);

    int blocks = (B + THREADS - 1) / THREADS;   // 256 blocks for B=262144
    loss_kernel<<<blocks, THREADS>>>(pred, tgt, out, B);
}

// round 15
// speedup vs baseline: 1.0295x; 1.0295x over previous
#include <cuda_runtime.h>

static constexpr int V = 1024;
static constexpr int THREADS = 1024;

__global__ void zero_out_kernel(float* out) {
    if (threadIdx.x == 0) out[0] = 0.0f;
}

__global__ void loss_kernel(const float* __restrict__ pred,
                            const int* __restrict__ tgt,
                            float* __restrict__ out, int B) {
    int i = blockIdx.x * blockDim.x + threadIdx.x;
    float v = 0.0f;
    if (i < B) {
        int t = __ldcg(&tgt[i]);
        float p = __ldcg(&pred[(size_t)i * V + t]);
        v = -__logf(p);
    }

    // intra-warp reduction
    #pragma unroll
    for (int o = 16; o > 0; o >>= 1)
        v += __shfl_down_sync(0xffffffffu, v, o);

    __shared__ float smem[THREADS >> 5];
    int lane = threadIdx.x & 31;
    int warp = threadIdx.x >> 5;
    if (lane == 0) smem[warp] = v;
    __syncthreads();

    // first warp reduces the 32 warp partials, one atomic per block
    if (warp == 0) {
        v = smem[lane];
        #pragma unroll
        for (int o = 16; o > 0; o >>= 1)
            v += __shfl_down_sync(0xffffffffu, v, o);
        if (lane == 0) atomicAdd(out, v);
    }
}

extern "C" void kernel_launch(void* const* d_in, const int* in_sizes, int n_in,
                              void* d_out, int out_size) {
    const float* pred = (const float*)d_in[0];
    const int* tgt = (const int*)d_in[1];
    float* out = (float*)d_out;
    int B = in_sizes[1];

    zero_out_kernel<<<1, 32>>>(out);

    int blocks = (B + THREADS - 1) / THREADS;   // 256 blocks for B=262144
    loss_kernel<<<blocks, THREADS>>>(pred, tgt, out, B);
}